// round 16
// baseline (speedup 1.0000x reference)
#include <cuda_runtime.h>
#include <cuda_fp16.h>
#include <math.h>
#include <stdint.h>

typedef uint32_t u32;
typedef unsigned long long u64;

#define LC 20
#define KGRID 1024

// ---- dynamic smem layout (byte offsets) ----
// per-warp staging: 64 segments of 160B with 16B pad every 4 segs = 10496B.
// A0 fp16 tile (32 rows x 80B = 2560B) aliases the start of the staging region.
#define WSTAGE     10496
#define OFF_STAGE  0
#define OFF_B0     41984      // 2kc*8nt*32lane * uint2 = 4096  (fp16)
#define OFF_B1F    46080      // 4kc*8nt*32lane * uint2 = 8192  (fp16)
#define OFF_W2     54272      // 64 * float4
#define OFF_B1P    55296      // 32 * float2
#define OFF_HG0    55552      // 512 floats
#define OFF_SC     57600      // 3 floats + pad
#define SMEM_BYTES 57616

__device__ __forceinline__ u32 smem_u32(const void* p) {
    u32 a;
    asm("{ .reg .u64 t; cvta.to.shared.u64 t, %1; cvt.u32.u64 %0, t; }" : "=r"(a) : "l"(p));
    return a;
}
#define CP_ASYNC16(dst, src) \
    asm volatile("cp.async.cg.shared.global [%0], [%1], 16;" :: "r"(dst), "l"(src) : "memory")
#define CP_COMMIT() asm volatile("cp.async.commit_group;" ::: "memory")
#define CP_WAIT0()  asm volatile("cp.async.wait_group 0;" ::: "memory")

// segment s byte offset inside a warp's staging region (conflict-free readback)
__device__ __forceinline__ u32 seg_off(int s) {
    return (u32)(s * 160 + (s >> 2) * 16);
}

// pack two floats into f16x2 (v0 -> lower half), RN
__device__ __forceinline__ u32 packh(float v0, float v1) {
    u32 h;
    asm("cvt.rn.f16x2.f32 %0, %1, %2;" : "=r"(h) : "f"(v1), "f"(v0));
    return h;
}

// packed f32x2 helpers
__device__ __forceinline__ u64 pk2(float a, float b) {
    u64 r; asm("mov.b64 %0, {%1, %2};" : "=l"(r) : "f"(a), "f"(b)); return r;
}
__device__ __forceinline__ void upk2(u64 v, float &a, float &b) {
    asm("mov.b64 {%0, %1}, %2;" : "=f"(a), "=f"(b) : "l"(v));
}
__device__ __forceinline__ void ffma2(u64 &acc, u64 a, u64 b) {
    asm("fma.rn.f32x2 %0, %1, %2, %0;" : "+l"(acc) : "l"(a), "l"(b));
}

__device__ __forceinline__ void mma16816(float d[4], const u32 a[4], u32 b0, u32 b1) {
    asm volatile(
        "mma.sync.aligned.m16n8k16.row.col.f32.f16.f16.f32 "
        "{%0,%1,%2,%3}, {%4,%5,%6,%7}, {%8,%9}, {%0,%1,%2,%3};"
        : "+f"(d[0]), "+f"(d[1]), "+f"(d[2]), "+f"(d[3])
        : "r"(a[0]), "r"(a[1]), "r"(a[2]), "r"(a[3]), "r"(b0), "r"(b1));
}

// compute lc0 cell base byte-offset for a point
__device__ __forceinline__ u32 cell_baseoff(float2 p) {
    float gx = p.x * 1023.0f, gy = p.y * 1023.0f;
    int ix = (int)floorf(gx); ix = max(0, min(ix, 1022));
    int iy = (int)floorf(gy); iy = max(0, min(iy, 1022));
    return (u32)(ix * KGRID + iy) * 80u;
}

// issue the 20 cp.async 16B transfers for one warp-tile (64 segs x 10 f4)
__device__ __forceinline__ void issue_prefetch(u32 baseoff, u32 stage_u32,
                                               const char* lc0b, int lane) {
    #pragma unroll
    for (int j = 0; j < 20; j++) {
        int fidx = j * 32 + lane;          // 0..639
        int s    = fidx / 10;              // segment 0..63
        int q    = fidx - s * 10;          // float4 within segment
        int pt   = s & 31;
        int half = s >> 5;                 // 0: row ix, 1: row ix+1 (+81920B)
        u32 off  = __shfl_sync(0xFFFFFFFFu, baseoff, pt) + (u32)half * 81920u + (u32)q * 16u;
        CP_ASYNC16(stage_u32 + seg_off(s) + (u32)q * 16u, lc0b + off);
    }
    CP_COMMIT();
}

__global__ void __launch_bounds__(128, 4)
rbf_mma_kernel(const float2* __restrict__ x,
               const float* __restrict__ hg0g, const float* __restrict__ hg1,
               const float* __restrict__ lc0,  const float* __restrict__ lcbg,
               const float* __restrict__ W0g, const float* __restrict__ b0g,
               const float* __restrict__ W1g, const float* __restrict__ b1g,
               const float* __restrict__ W2g, const float* __restrict__ b2g,
               const float* __restrict__ a0g, const float* __restrict__ a1g,
               const float* __restrict__ a2g,
               float* __restrict__ out, int n, int ntiles)
{
    extern __shared__ char base[];
    const int tid = threadIdx.x;
    const int wid = tid >> 5, lane = tid & 31;
    const int g = lane >> 2, t = lane & 3;
    const float a0 = a0g[0], a1 = a1g[0], a2 = a2g[0];

    uint2*  sB0  = (uint2*)(base + OFF_B0);
    uint2*  sB1  = (uint2*)(base + OFF_B1F);
    float4* sW2  = (float4*)(base + OFF_W2);
    float2* sb1p = (float2*)(base + OFF_B1P);
    float*  shg0 = (float*)(base + OFF_HG0);
    float*  ssc  = (float*)(base + OFF_SC);

    char* stage = base + OFF_STAGE + wid * WSTAGE;   // per-warp staging / A0 region
    const u32 stage_u32 = smem_u32(stage);
    u32*  sA0h  = (u32*)stage;                       // 32 rows x 20 u32 (aliases staging)

    // ---- one-time init ----
    for (int k = tid; k < 512; k += 128) shg0[k] = hg0g[k];
    if (tid < 64)
        sW2[tid] = make_float4(a2 * W2g[tid], a2 * W2g[64 + tid], a2 * W2g[128 + tid], 0.0f);
    if (tid < 32) {
        int nt_ = tid >> 2, t_ = tid & 3;
        int c0 = nt_ * 8 + 2 * t_;
        sb1p[tid] = make_float2(a1 * b1g[c0], a1 * b1g[c0 + 1]);
    }
    if (tid < 3) ssc[tid] = a2 * b2g[tid];

    // B0 fragments (fp16): B0[k][n]; k<24: a0*W0[n][k];
    // k==24: a0*(b0[n]+lcb@W0[n]); else 0
    for (int s = tid; s < 512; s += 128) {
        int ln = s & 31, nt_ = (s >> 5) & 7, kc = s >> 8;
        int gg = ln >> 2, tt = ln & 3;
        int nn = nt_ * 8 + gg;
        int k0 = kc * 16 + 2 * tt;
        float w[4];
        #pragma unroll
        for (int q = 0; q < 4; q++) {
            int k = k0 + (q >> 1) * 8 + (q & 1);
            float v;
            if (k < 24) v = a0 * W0g[nn * 24 + k];
            else if (k == 24) {
                float acc = b0g[nn];
                for (int kk = 0; kk < 24; kk++) acc += lcbg[kk] * W0g[nn * 24 + kk];
                v = a0 * acc;
            } else v = 0.0f;
            w[q] = v;
        }
        sB0[s] = make_uint2(packh(w[0], w[1]), packh(w[2], w[3]));
    }
    // B1 fragments (fp16): B1[k][n] = a1*W1[n][k]
    for (int s = tid; s < 1024; s += 128) {
        int ln = s & 31, nt_ = (s >> 5) & 7, kc = s >> 8;
        int gg = ln >> 2, tt = ln & 3;
        int nn = nt_ * 8 + gg;
        int k0 = kc * 16 + 2 * tt;
        float w0v = a1 * W1g[nn * 64 + k0];
        float w1v = a1 * W1g[nn * 64 + k0 + 1];
        float w2v = a1 * W1g[nn * 64 + k0 + 8];
        float w3v = a1 * W1g[nn * 64 + k0 + 9];
        sB1[s] = make_uint2(packh(w0v, w1v), packh(w2v, w3v));
    }
    __syncthreads();

    const float c0s = ssc[0], c1s = ssc[1], c2s = ssc[2];
    const int gw = blockIdx.x * 4 + wid;
    const int nw = gridDim.x * 4;
    const char* lc0b = (const char*)lc0;

    // ---- prologue: prefetch first tile ----
    float2 p_cur = make_float2(0.f, 0.f);
    if (gw < ntiles) {
        int i = gw * 32 + lane;
        p_cur = x[(i < n) ? i : (n - 1)];
        issue_prefetch(cell_baseoff(p_cur), stage_u32, lc0b, lane);
    }

    for (int tile = gw; tile < ntiles; tile += nw) {
        // ---- next-tile point + prefetch base (issued later, overlaps MMA) ----
        int tnext = tile + nw;
        bool has_next = (tnext < ntiles);
        float2 p_next = p_cur;
        u32 baseoff_next = 0;
        if (has_next) {
            int i2 = tnext * 32 + lane;
            p_next = x[(i2 < n) ? i2 : (n - 1)];
            baseoff_next = cell_baseoff(p_next);
        }

        // ---- bilinear weights for current point ----
        float w00, w01, w10, w11;
        {
            float gx = p_cur.x * 1023.0f, gy = p_cur.y * 1023.0f;
            int ix = (int)floorf(gx); ix = max(0, min(ix, 1022));
            int iy = (int)floorf(gy); iy = max(0, min(iy, 1022));
            float fx = gx - (float)ix, fy = gy - (float)iy;
            // weights sum to 1 (+-1ulp); reference normalize shifts them ~1e-7 -> dropped
            w00 = (1.0f - fx) * (1.0f - fy);
            w01 = (1.0f - fx) * fy;
            w10 = fx * (1.0f - fy);
            w11 = fx * fy;
        }

        // ---- hashgrid level 1 loads issued early (latency hides under wait) ----
        float2 g00, g01, g10, g11;
        float hv00, hv01, hv10, hv11;
        {
            float gx = p_cur.x * 2047.0f, gy = p_cur.y * 2047.0f;
            int ix = (int)floorf(gx); ix = max(0, min(ix, 2046));
            int iy = (int)floorf(gy); iy = max(0, min(iy, 2046));
            float fx = gx - (float)ix, fy = gy - (float)iy;
            hv00 = (1.0f - fx) * (1.0f - fy); hv01 = (1.0f - fx) * fy;
            hv10 = fx * (1.0f - fy);          hv11 = fx * fy;
            const float2* tt = (const float2*)hg1;
            g00 = tt[ix * 2048 + iy];       g01 = tt[ix * 2048 + iy + 1];
            g10 = tt[(ix + 1) * 2048 + iy]; g11 = tt[(ix + 1) * 2048 + iy + 1];
        }

        float h0[24];
        // ---- wait for prefetched lc0 staging, then conflict-free readback ----
        CP_WAIT0();
        __syncwarp();
        {
            const char* s0p = stage + seg_off(lane);
            const char* s1p = stage + seg_off(32 + lane);
            u64 W00 = pk2(w00, w00), W01 = pk2(w01, w01);
            u64 W10 = pk2(w10, w10), W11 = pk2(w11, w11);
            #pragma unroll
            for (int q = 0; q < 5; q++) {
                float4 c00 = *(const float4*)(s0p + q * 16);
                float4 c01 = *(const float4*)(s0p + (q + 5) * 16);
                float4 c10 = *(const float4*)(s1p + q * 16);
                float4 c11 = *(const float4*)(s1p + (q + 5) * 16);
                u64 a01 = 0ull, a23 = 0ull;
                ffma2(a01, pk2(c00.x, c00.y), W00); ffma2(a23, pk2(c00.z, c00.w), W00);
                ffma2(a01, pk2(c01.x, c01.y), W01); ffma2(a23, pk2(c01.z, c01.w), W01);
                ffma2(a01, pk2(c10.x, c10.y), W10); ffma2(a23, pk2(c10.z, c10.w), W10);
                ffma2(a01, pk2(c11.x, c11.y), W11); ffma2(a23, pk2(c11.z, c11.w), W11);
                upk2(a01, h0[4 * q + 0], h0[4 * q + 1]);
                upk2(a23, h0[4 * q + 2], h0[4 * q + 3]);
            }
        }
        // hashgrid level 0 (res 16) from shared
        {
            float gx = p_cur.x * 15.0f, gy = p_cur.y * 15.0f;
            int ix = (int)floorf(gx); ix = max(0, min(ix, 14));
            int iy = (int)floorf(gy); iy = max(0, min(iy, 14));
            float fx = gx - (float)ix, fy = gy - (float)iy;
            float v00 = (1.0f - fx) * (1.0f - fy), v01 = (1.0f - fx) * fy;
            float v10 = fx * (1.0f - fy),          v11 = fx * fy;
            const float2* tt = (const float2*)shg0;
            float2 c00 = tt[ix * 16 + iy],       c01 = tt[ix * 16 + iy + 1];
            float2 c10 = tt[(ix + 1) * 16 + iy], c11 = tt[(ix + 1) * 16 + iy + 1];
            h0[20] = v00 * c00.x + v01 * c01.x + v10 * c10.x + v11 * c11.x;
            h0[21] = v00 * c00.y + v01 * c01.y + v10 * c10.y + v11 * c11.y;
        }
        h0[22] = hv00 * g00.x + hv01 * g01.x + hv10 * g10.x + hv11 * g11.x;
        h0[23] = hv00 * g00.y + hv01 * g01.y + hv10 * g10.y + hv11 * g11.y;
        __syncwarp();   // staged reads complete before A0 overwrites the region

        // ---- write this lane's A0 row (cols 0..23 + const tail), fp16 hi only ----
        {
            u32 rh[12];
            #pragma unroll
            for (int q = 0; q < 12; q++)
                rh[q] = packh(h0[2 * q], h0[2 * q + 1]);
            uint4* rh4 = (uint4*)(sA0h + lane * 20);
            #pragma unroll
            for (int q = 0; q < 3; q++)
                rh4[q] = make_uint4(rh[4 * q], rh[4 * q + 1], rh[4 * q + 2], rh[4 * q + 3]);
            // tail: bias f16(1.0) at col 24, zeros at 25..31 (staging overwrote it)
            rh4[3] = make_uint4(0x00003C00u, 0u, 0u, 0u);
            sA0h[lane * 20 + 16] = 0u; sA0h[lane * 20 + 17] = 0u;
            sA0h[lane * 20 + 18] = 0u; sA0h[lane * 20 + 19] = 0u;
        }
        __syncwarp();

        // ---- load A0 fragments (hi only) for BOTH m halves ----
        u32 Ah[2][2][4];   // [m][kc][4]
        #pragma unroll
        for (int m = 0; m < 2; m++) {
            int ridx = (16 * m + g) * 20 + t;
            #pragma unroll
            for (int kc = 0; kc < 2; kc++) {
                Ah[m][kc][0] = sA0h[ridx + 8 * kc];
                Ah[m][kc][1] = sA0h[ridx + 8 * kc + 160];
                Ah[m][kc][2] = sA0h[ridx + 8 * kc + 4];
                Ah[m][kc][3] = sA0h[ridx + 8 * kc + 164];
            }
        }
        __syncwarp();   // all frag reads done before prefetch overwrites staging

        // ---- prefetch next tile's lc0 into staging; overlaps all MMA work ----
        if (has_next)
            issue_prefetch(baseoff_next, stage_u32, lc0b, lane);

        // ---- layer 0: nt-pairs x both m = 4 independent chains, A hi-only ----
        u32 A1h[2][4][4];   // [m][kc1][4]
        #pragma unroll
        for (int ntp = 0; ntp < 4; ntp++) {
            float d[2][2][4];             // [ntq][m][4]
            #pragma unroll
            for (int q_ = 0; q_ < 2; q_++)
                #pragma unroll
                for (int m = 0; m < 2; m++)
                    d[q_][m][0] = d[q_][m][1] = d[q_][m][2] = d[q_][m][3] = 0.f;
            #pragma unroll
            for (int kc = 0; kc < 2; kc++) {
                uint2 Ba = sB0[(kc * 8 + 2 * ntp) * 32 + lane];
                uint2 Bb = sB0[(kc * 8 + 2 * ntp + 1) * 32 + lane];
                mma16816(d[0][0], Ah[0][kc], Ba.x, Ba.y);
                mma16816(d[1][0], Ah[0][kc], Bb.x, Bb.y);
                mma16816(d[0][1], Ah[1][kc], Ba.x, Ba.y);
                mma16816(d[1][1], Ah[1][kc], Bb.x, Bb.y);
            }
            #pragma unroll
            for (int q_ = 0; q_ < 2; q_++) {
                int nt = 2 * ntp + q_;
                int kc1 = nt >> 1, hf = nt & 1;
                #pragma unroll
                for (int m = 0; m < 2; m++) {
                    float v0 = fmaxf(d[q_][m][0], 0.f), v1 = fmaxf(d[q_][m][1], 0.f);
                    float v2 = fmaxf(d[q_][m][2], 0.f), v3 = fmaxf(d[q_][m][3], 0.f);
                    A1h[m][kc1][hf ? 2 : 0] = packh(v0, v1);
                    A1h[m][kc1][hf ? 3 : 1] = packh(v2, v3);
                }
            }
        }

        // ---- layer 1 + fused output layer, A hi-only, 4-chain interleave ----
        float o[2][2][3];
        #pragma unroll
        for (int m = 0; m < 2; m++)
            #pragma unroll
            for (int r = 0; r < 2; r++)
                o[m][r][0] = o[m][r][1] = o[m][r][2] = 0.0f;

        #pragma unroll
        for (int ntp = 0; ntp < 4; ntp++) {
            float d[2][2][4];
            #pragma unroll
            for (int q_ = 0; q_ < 2; q_++)
                #pragma unroll
                for (int m = 0; m < 2; m++)
                    d[q_][m][0] = d[q_][m][1] = d[q_][m][2] = d[q_][m][3] = 0.f;
            #pragma unroll
            for (int kc = 0; kc < 4; kc++) {
                uint2 Ba = sB1[(kc * 8 + 2 * ntp) * 32 + lane];
                uint2 Bb = sB1[(kc * 8 + 2 * ntp + 1) * 32 + lane];
                mma16816(d[0][0], A1h[0][kc], Ba.x, Ba.y);
                mma16816(d[1][0], A1h[0][kc], Bb.x, Bb.y);
                mma16816(d[0][1], A1h[1][kc], Ba.x, Ba.y);
                mma16816(d[1][1], A1h[1][kc], Bb.x, Bb.y);
            }
            #pragma unroll
            for (int q_ = 0; q_ < 2; q_++) {
                int nt = 2 * ntp + q_;
                float2 bp = sb1p[nt * 4 + t];
                float4 wa = sW2[nt * 8 + 2 * t];
                float4 wb = sW2[nt * 8 + 2 * t + 1];
                #pragma unroll
                for (int m = 0; m < 2; m++) {
                    float v0 = fmaxf(d[q_][m][0] + bp.x, 0.f);
                    float v1 = fmaxf(d[q_][m][1] + bp.y, 0.f);
                    float v2 = fmaxf(d[q_][m][2] + bp.x, 0.f);
                    float v3 = fmaxf(d[q_][m][3] + bp.y, 0.f);
                    o[m][0][0] += v0 * wa.x + v1 * wb.x;
                    o[m][0][1] += v0 * wa.y + v1 * wb.y;
                    o[m][0][2] += v0 * wa.z + v1 * wb.z;
                    o[m][1][0] += v2 * wa.x + v3 * wb.x;
                    o[m][1][1] += v2 * wa.y + v3 * wb.y;
                    o[m][1][2] += v2 * wa.z + v3 * wb.z;
                }
            }
        }

        // reduce partials across the 4 lanes of each group (cols are t-partitioned)
        #pragma unroll
        for (int m = 0; m < 2; m++)
            #pragma unroll
            for (int r = 0; r < 2; r++)
                #pragma unroll
                for (int c = 0; c < 3; c++) {
                    float v = o[m][r][c];
                    v += __shfl_xor_sync(0xFFFFFFFFu, v, 1);
                    v += __shfl_xor_sync(0xFFFFFFFFu, v, 2);
                    o[m][r][c] = v;
                }

        if (t == 0) {
            #pragma unroll
            for (int m = 0; m < 2; m++)
                #pragma unroll
                for (int r = 0; r < 2; r++) {
                    int idx = tile * 32 + 16 * m + 8 * r + g;
                    if (idx < n) {
                        out[3 * idx + 0] = o[m][r][0] + c0s;
                        out[3 * idx + 1] = o[m][r][1] + c1s;
                        out[3 * idx + 2] = o[m][r][2] + c2s;
                    }
                }
        }

        p_cur = p_next;
    }
}

extern "C" void kernel_launch(void* const* d_in, const int* in_sizes, int n_in,
                              void* d_out, int out_size)
{
    const float2* x    = (const float2*)d_in[0];
    const float*  hg0  = (const float*)d_in[1];
    const float*  hg1  = (const float*)d_in[2];
    // d_in[3] = kc0 (regular grid, analytic), d_in[4] = ks0 (== K-1)
    const float*  lc0  = (const float*)d_in[5];
    const float*  lcb0 = (const float*)d_in[6];
    const float*  W0   = (const float*)d_in[7];
    const float*  b0   = (const float*)d_in[8];
    const float*  W1   = (const float*)d_in[9];
    const float*  b1   = (const float*)d_in[10];
    const float*  W2   = (const float*)d_in[11];
    const float*  b2   = (const float*)d_in[12];
    const float*  a0   = (const float*)d_in[13];
    const float*  a1   = (const float*)d_in[14];
    const float*  a2   = (const float*)d_in[15];
    float* out = (float*)d_out;

    const int n = in_sizes[0] / 2;
    const int ntiles = (n + 31) / 32;
    int grid = 592;                       // 148 SMs x 4 blocks
    int maxg = (ntiles + 3) / 4;
    if (grid > maxg) grid = maxg;

    cudaFuncSetAttribute(rbf_mma_kernel, cudaFuncAttributeMaxDynamicSharedMemorySize, SMEM_BYTES);
    rbf_mma_kernel<<<grid, 128, SMEM_BYTES>>>(x, hg0, hg1, lc0, lcb0,
                                              W0, b0, W1, b1, W2, b2,
                                              a0, a1, a2, out, n, ntiles);
}

// round 17
// speedup vs baseline: 1.0751x; 1.0751x over previous
#include <cuda_runtime.h>
#include <cuda_fp16.h>
#include <math.h>
#include <stdint.h>

typedef uint32_t u32;
typedef unsigned long long u64;

#define LC 20
#define KGRID 1024

// ---- dynamic smem layout (byte offsets) ----
// per-warp staging: 64 segments of 160B with 16B pad every 8 segs = 10368B.
// (4-way-conflicted readback; costs ~120cyc/tile, saves 272B -> 4 blocks fit.)
// A0 fp16 tile (32 rows x 80B = 2560B) aliases the start of the staging region.
#define WSTAGE     10368
#define OFF_STAGE  0
#define OFF_B0     41472      // 2kc*8nt*32lane * uint2 = 4096  (fp16)
#define OFF_B1F    45568      // 4kc*8nt*32lane * uint2 = 8192  (fp16)
#define OFF_W2     53760      // 64 * float4
#define OFF_B1P    54784      // 32 * float2
#define OFF_HG0    55040      // 512 floats
#define OFF_SC     57088      // 3 floats + pad
#define SMEM_BYTES 57104      // +1KB HW reserve -> 58128/block; x4 = 232512 <= 233472

__device__ __forceinline__ u32 smem_u32(const void* p) {
    u32 a;
    asm("{ .reg .u64 t; cvta.to.shared.u64 t, %1; cvt.u32.u64 %0, t; }" : "=r"(a) : "l"(p));
    return a;
}
#define CP_ASYNC16(dst, src) \
    asm volatile("cp.async.cg.shared.global [%0], [%1], 16;" :: "r"(dst), "l"(src) : "memory")
#define CP_COMMIT() asm volatile("cp.async.commit_group;" ::: "memory")
#define CP_WAIT0()  asm volatile("cp.async.wait_group 0;" ::: "memory")

// segment s byte offset inside a warp's staging region
__device__ __forceinline__ u32 seg_off(int s) {
    return (u32)(s * 160 + (s >> 3) * 16);
}

// pack two floats into f16x2 (v0 -> lower half), RN
__device__ __forceinline__ u32 packh(float v0, float v1) {
    u32 h;
    asm("cvt.rn.f16x2.f32 %0, %1, %2;" : "=r"(h) : "f"(v1), "f"(v0));
    return h;
}

// packed f32x2 helpers
__device__ __forceinline__ u64 pk2(float a, float b) {
    u64 r; asm("mov.b64 %0, {%1, %2};" : "=l"(r) : "f"(a), "f"(b)); return r;
}
__device__ __forceinline__ void upk2(u64 v, float &a, float &b) {
    asm("mov.b64 {%0, %1}, %2;" : "=f"(a), "=f"(b) : "l"(v));
}
__device__ __forceinline__ void ffma2(u64 &acc, u64 a, u64 b) {
    asm("fma.rn.f32x2 %0, %1, %2, %0;" : "+l"(acc) : "l"(a), "l"(b));
}

__device__ __forceinline__ void mma16816(float d[4], const u32 a[4], u32 b0, u32 b1) {
    asm volatile(
        "mma.sync.aligned.m16n8k16.row.col.f32.f16.f16.f32 "
        "{%0,%1,%2,%3}, {%4,%5,%6,%7}, {%8,%9}, {%0,%1,%2,%3};"
        : "+f"(d[0]), "+f"(d[1]), "+f"(d[2]), "+f"(d[3])
        : "r"(a[0]), "r"(a[1]), "r"(a[2]), "r"(a[3]), "r"(b0), "r"(b1));
}

// compute lc0 cell base byte-offset for a point
__device__ __forceinline__ u32 cell_baseoff(float2 p) {
    float gx = p.x * 1023.0f, gy = p.y * 1023.0f;
    int ix = (int)floorf(gx); ix = max(0, min(ix, 1022));
    int iy = (int)floorf(gy); iy = max(0, min(iy, 1022));
    return (u32)(ix * KGRID + iy) * 80u;
}

// issue the 20 cp.async 16B transfers for one warp-tile (64 segs x 10 f4)
__device__ __forceinline__ void issue_prefetch(u32 baseoff, u32 stage_u32,
                                               const char* lc0b, int lane) {
    #pragma unroll
    for (int j = 0; j < 20; j++) {
        int fidx = j * 32 + lane;          // 0..639
        int s    = fidx / 10;              // segment 0..63
        int q    = fidx - s * 10;          // float4 within segment
        int pt   = s & 31;
        int half = s >> 5;                 // 0: row ix, 1: row ix+1 (+81920B)
        u32 off  = __shfl_sync(0xFFFFFFFFu, baseoff, pt) + (u32)half * 81920u + (u32)q * 16u;
        CP_ASYNC16(stage_u32 + seg_off(s) + (u32)q * 16u, lc0b + off);
    }
    CP_COMMIT();
}

__global__ void __launch_bounds__(128, 4)
rbf_mma_kernel(const float2* __restrict__ x,
               const float* __restrict__ hg0g, const float* __restrict__ hg1,
               const float* __restrict__ lc0,  const float* __restrict__ lcbg,
               const float* __restrict__ W0g, const float* __restrict__ b0g,
               const float* __restrict__ W1g, const float* __restrict__ b1g,
               const float* __restrict__ W2g, const float* __restrict__ b2g,
               const float* __restrict__ a0g, const float* __restrict__ a1g,
               const float* __restrict__ a2g,
               float* __restrict__ out, int n, int ntiles)
{
    extern __shared__ char base[];
    const int tid = threadIdx.x;
    const int wid = tid >> 5, lane = tid & 31;
    const int g = lane >> 2, t = lane & 3;
    const float a0 = a0g[0], a1 = a1g[0], a2 = a2g[0];

    uint2*  sB0  = (uint2*)(base + OFF_B0);
    uint2*  sB1  = (uint2*)(base + OFF_B1F);
    float4* sW2  = (float4*)(base + OFF_W2);
    float2* sb1p = (float2*)(base + OFF_B1P);
    float*  shg0 = (float*)(base + OFF_HG0);
    float*  ssc  = (float*)(base + OFF_SC);

    char* stage = base + OFF_STAGE + wid * WSTAGE;   // per-warp staging / A0 region
    const u32 stage_u32 = smem_u32(stage);
    u32*  sA0h  = (u32*)stage;                       // 32 rows x 20 u32 (aliases staging)

    // ---- one-time init ----
    for (int k = tid; k < 512; k += 128) shg0[k] = hg0g[k];
    if (tid < 64)
        sW2[tid] = make_float4(a2 * W2g[tid], a2 * W2g[64 + tid], a2 * W2g[128 + tid], 0.0f);
    if (tid < 32) {
        int nt_ = tid >> 2, t_ = tid & 3;
        int c0 = nt_ * 8 + 2 * t_;
        sb1p[tid] = make_float2(a1 * b1g[c0], a1 * b1g[c0 + 1]);
    }
    if (tid < 3) ssc[tid] = a2 * b2g[tid];

    // B0 fragments (fp16): B0[k][n]; k<24: a0*W0[n][k];
    // k==24: a0*(b0[n]+lcb@W0[n]); else 0
    for (int s = tid; s < 512; s += 128) {
        int ln = s & 31, nt_ = (s >> 5) & 7, kc = s >> 8;
        int gg = ln >> 2, tt = ln & 3;
        int nn = nt_ * 8 + gg;
        int k0 = kc * 16 + 2 * tt;
        float w[4];
        #pragma unroll
        for (int q = 0; q < 4; q++) {
            int k = k0 + (q >> 1) * 8 + (q & 1);
            float v;
            if (k < 24) v = a0 * W0g[nn * 24 + k];
            else if (k == 24) {
                float acc = b0g[nn];
                for (int kk = 0; kk < 24; kk++) acc += lcbg[kk] * W0g[nn * 24 + kk];
                v = a0 * acc;
            } else v = 0.0f;
            w[q] = v;
        }
        sB0[s] = make_uint2(packh(w[0], w[1]), packh(w[2], w[3]));
    }
    // B1 fragments (fp16): B1[k][n] = a1*W1[n][k]
    for (int s = tid; s < 1024; s += 128) {
        int ln = s & 31, nt_ = (s >> 5) & 7, kc = s >> 8;
        int gg = ln >> 2, tt = ln & 3;
        int nn = nt_ * 8 + gg;
        int k0 = kc * 16 + 2 * tt;
        float w0v = a1 * W1g[nn * 64 + k0];
        float w1v = a1 * W1g[nn * 64 + k0 + 1];
        float w2v = a1 * W1g[nn * 64 + k0 + 8];
        float w3v = a1 * W1g[nn * 64 + k0 + 9];
        sB1[s] = make_uint2(packh(w0v, w1v), packh(w2v, w3v));
    }
    __syncthreads();

    const float c0s = ssc[0], c1s = ssc[1], c2s = ssc[2];
    const int gw = blockIdx.x * 4 + wid;
    const int nw = gridDim.x * 4;
    const char* lc0b = (const char*)lc0;

    // ---- prologue: prefetch first tile ----
    float2 p_cur = make_float2(0.f, 0.f);
    if (gw < ntiles) {
        int i = gw * 32 + lane;
        p_cur = x[(i < n) ? i : (n - 1)];
        issue_prefetch(cell_baseoff(p_cur), stage_u32, lc0b, lane);
    }

    for (int tile = gw; tile < ntiles; tile += nw) {
        // ---- next-tile point + prefetch base (issued later, overlaps MMA) ----
        int tnext = tile + nw;
        bool has_next = (tnext < ntiles);
        float2 p_next = p_cur;
        u32 baseoff_next = 0;
        if (has_next) {
            int i2 = tnext * 32 + lane;
            p_next = x[(i2 < n) ? i2 : (n - 1)];
            baseoff_next = cell_baseoff(p_next);
        }

        // ---- bilinear weights for current point ----
        float w00, w01, w10, w11;
        {
            float gx = p_cur.x * 1023.0f, gy = p_cur.y * 1023.0f;
            int ix = (int)floorf(gx); ix = max(0, min(ix, 1022));
            int iy = (int)floorf(gy); iy = max(0, min(iy, 1022));
            float fx = gx - (float)ix, fy = gy - (float)iy;
            // weights sum to 1 (+-1ulp); reference normalize shifts them ~1e-7 -> dropped
            w00 = (1.0f - fx) * (1.0f - fy);
            w01 = (1.0f - fx) * fy;
            w10 = fx * (1.0f - fy);
            w11 = fx * fy;
        }

        // ---- hashgrid level 1 loads issued early (latency hides under wait) ----
        float2 g00, g01, g10, g11;
        float hv00, hv01, hv10, hv11;
        {
            float gx = p_cur.x * 2047.0f, gy = p_cur.y * 2047.0f;
            int ix = (int)floorf(gx); ix = max(0, min(ix, 2046));
            int iy = (int)floorf(gy); iy = max(0, min(iy, 2046));
            float fx = gx - (float)ix, fy = gy - (float)iy;
            hv00 = (1.0f - fx) * (1.0f - fy); hv01 = (1.0f - fx) * fy;
            hv10 = fx * (1.0f - fy);          hv11 = fx * fy;
            const float2* tt = (const float2*)hg1;
            g00 = tt[ix * 2048 + iy];       g01 = tt[ix * 2048 + iy + 1];
            g10 = tt[(ix + 1) * 2048 + iy]; g11 = tt[(ix + 1) * 2048 + iy + 1];
        }

        float h0[24];
        // ---- wait for prefetched lc0 staging, then readback ----
        CP_WAIT0();
        __syncwarp();
        {
            const char* s0p = stage + seg_off(lane);
            const char* s1p = stage + seg_off(32 + lane);
            u64 W00 = pk2(w00, w00), W01 = pk2(w01, w01);
            u64 W10 = pk2(w10, w10), W11 = pk2(w11, w11);
            #pragma unroll
            for (int q = 0; q < 5; q++) {
                float4 c00 = *(const float4*)(s0p + q * 16);
                float4 c01 = *(const float4*)(s0p + (q + 5) * 16);
                float4 c10 = *(const float4*)(s1p + q * 16);
                float4 c11 = *(const float4*)(s1p + (q + 5) * 16);
                u64 a01 = 0ull, a23 = 0ull;
                ffma2(a01, pk2(c00.x, c00.y), W00); ffma2(a23, pk2(c00.z, c00.w), W00);
                ffma2(a01, pk2(c01.x, c01.y), W01); ffma2(a23, pk2(c01.z, c01.w), W01);
                ffma2(a01, pk2(c10.x, c10.y), W10); ffma2(a23, pk2(c10.z, c10.w), W10);
                ffma2(a01, pk2(c11.x, c11.y), W11); ffma2(a23, pk2(c11.z, c11.w), W11);
                upk2(a01, h0[4 * q + 0], h0[4 * q + 1]);
                upk2(a23, h0[4 * q + 2], h0[4 * q + 3]);
            }
        }
        // hashgrid level 0 (res 16) from shared
        {
            float gx = p_cur.x * 15.0f, gy = p_cur.y * 15.0f;
            int ix = (int)floorf(gx); ix = max(0, min(ix, 14));
            int iy = (int)floorf(gy); iy = max(0, min(iy, 14));
            float fx = gx - (float)ix, fy = gy - (float)iy;
            float v00 = (1.0f - fx) * (1.0f - fy), v01 = (1.0f - fx) * fy;
            float v10 = fx * (1.0f - fy),          v11 = fx * fy;
            const float2* tt = (const float2*)shg0;
            float2 c00 = tt[ix * 16 + iy],       c01 = tt[ix * 16 + iy + 1];
            float2 c10 = tt[(ix + 1) * 16 + iy], c11 = tt[(ix + 1) * 16 + iy + 1];
            h0[20] = v00 * c00.x + v01 * c01.x + v10 * c10.x + v11 * c11.x;
            h0[21] = v00 * c00.y + v01 * c01.y + v10 * c10.y + v11 * c11.y;
        }
        h0[22] = hv00 * g00.x + hv01 * g01.x + hv10 * g10.x + hv11 * g11.x;
        h0[23] = hv00 * g00.y + hv01 * g01.y + hv10 * g10.y + hv11 * g11.y;
        __syncwarp();   // staged reads complete before A0 overwrites the region

        // ---- write this lane's A0 row (cols 0..23 + const tail), fp16 hi only ----
        {
            u32 rh[12];
            #pragma unroll
            for (int q = 0; q < 12; q++)
                rh[q] = packh(h0[2 * q], h0[2 * q + 1]);
            uint4* rh4 = (uint4*)(sA0h + lane * 20);
            #pragma unroll
            for (int q = 0; q < 3; q++)
                rh4[q] = make_uint4(rh[4 * q], rh[4 * q + 1], rh[4 * q + 2], rh[4 * q + 3]);
            // tail: bias f16(1.0) at col 24, zeros at 25..31 (staging overwrote it)
            rh4[3] = make_uint4(0x00003C00u, 0u, 0u, 0u);
            sA0h[lane * 20 + 16] = 0u; sA0h[lane * 20 + 17] = 0u;
            sA0h[lane * 20 + 18] = 0u; sA0h[lane * 20 + 19] = 0u;
        }
        __syncwarp();

        // ---- load A0 fragments (hi only) for BOTH m halves ----
        u32 Ah[2][2][4];   // [m][kc][4]
        #pragma unroll
        for (int m = 0; m < 2; m++) {
            int ridx = (16 * m + g) * 20 + t;
            #pragma unroll
            for (int kc = 0; kc < 2; kc++) {
                Ah[m][kc][0] = sA0h[ridx + 8 * kc];
                Ah[m][kc][1] = sA0h[ridx + 8 * kc + 160];
                Ah[m][kc][2] = sA0h[ridx + 8 * kc + 4];
                Ah[m][kc][3] = sA0h[ridx + 8 * kc + 164];
            }
        }
        __syncwarp();   // all frag reads done before prefetch overwrites staging

        // ---- prefetch next tile's lc0 into staging; overlaps all MMA work ----
        if (has_next)
            issue_prefetch(baseoff_next, stage_u32, lc0b, lane);

        // ---- layer 0: nt-pairs x both m = 4 independent chains, A hi-only ----
        u32 A1h[2][4][4];   // [m][kc1][4]
        #pragma unroll
        for (int ntp = 0; ntp < 4; ntp++) {
            float d[2][2][4];             // [ntq][m][4]
            #pragma unroll
            for (int q_ = 0; q_ < 2; q_++)
                #pragma unroll
                for (int m = 0; m < 2; m++)
                    d[q_][m][0] = d[q_][m][1] = d[q_][m][2] = d[q_][m][3] = 0.f;
            #pragma unroll
            for (int kc = 0; kc < 2; kc++) {
                uint2 Ba = sB0[(kc * 8 + 2 * ntp) * 32 + lane];
                uint2 Bb = sB0[(kc * 8 + 2 * ntp + 1) * 32 + lane];
                mma16816(d[0][0], Ah[0][kc], Ba.x, Ba.y);
                mma16816(d[1][0], Ah[0][kc], Bb.x, Bb.y);
                mma16816(d[0][1], Ah[1][kc], Ba.x, Ba.y);
                mma16816(d[1][1], Ah[1][kc], Bb.x, Bb.y);
            }
            #pragma unroll
            for (int q_ = 0; q_ < 2; q_++) {
                int nt = 2 * ntp + q_;
                int kc1 = nt >> 1, hf = nt & 1;
                #pragma unroll
                for (int m = 0; m < 2; m++) {
                    float v0 = fmaxf(d[q_][m][0], 0.f), v1 = fmaxf(d[q_][m][1], 0.f);
                    float v2 = fmaxf(d[q_][m][2], 0.f), v3 = fmaxf(d[q_][m][3], 0.f);
                    A1h[m][kc1][hf ? 2 : 0] = packh(v0, v1);
                    A1h[m][kc1][hf ? 3 : 1] = packh(v2, v3);
                }
            }
        }

        // ---- layer 1 + fused output layer, A hi-only, 4-chain interleave ----
        float o[2][2][3];
        #pragma unroll
        for (int m = 0; m < 2; m++)
            #pragma unroll
            for (int r = 0; r < 2; r++)
                o[m][r][0] = o[m][r][1] = o[m][r][2] = 0.0f;

        #pragma unroll
        for (int ntp = 0; ntp < 4; ntp++) {
            float d[2][2][4];
            #pragma unroll
            for (int q_ = 0; q_ < 2; q_++)
                #pragma unroll
                for (int m = 0; m < 2; m++)
                    d[q_][m][0] = d[q_][m][1] = d[q_][m][2] = d[q_][m][3] = 0.f;
            #pragma unroll
            for (int kc = 0; kc < 4; kc++) {
                uint2 Ba = sB1[(kc * 8 + 2 * ntp) * 32 + lane];
                uint2 Bb = sB1[(kc * 8 + 2 * ntp + 1) * 32 + lane];
                mma16816(d[0][0], A1h[0][kc], Ba.x, Ba.y);
                mma16816(d[1][0], A1h[0][kc], Bb.x, Bb.y);
                mma16816(d[0][1], A1h[1][kc], Ba.x, Ba.y);
                mma16816(d[1][1], A1h[1][kc], Bb.x, Bb.y);
            }
            #pragma unroll
            for (int q_ = 0; q_ < 2; q_++) {
                int nt = 2 * ntp + q_;
                float2 bp = sb1p[nt * 4 + t];
                float4 wa = sW2[nt * 8 + 2 * t];
                float4 wb = sW2[nt * 8 + 2 * t + 1];
                #pragma unroll
                for (int m = 0; m < 2; m++) {
                    float v0 = fmaxf(d[q_][m][0] + bp.x, 0.f);
                    float v1 = fmaxf(d[q_][m][1] + bp.y, 0.f);
                    float v2 = fmaxf(d[q_][m][2] + bp.x, 0.f);
                    float v3 = fmaxf(d[q_][m][3] + bp.y, 0.f);
                    o[m][0][0] += v0 * wa.x + v1 * wb.x;
                    o[m][0][1] += v0 * wa.y + v1 * wb.y;
                    o[m][0][2] += v0 * wa.z + v1 * wb.z;
                    o[m][1][0] += v2 * wa.x + v3 * wb.x;
                    o[m][1][1] += v2 * wa.y + v3 * wb.y;
                    o[m][1][2] += v2 * wa.z + v3 * wb.z;
                }
            }
        }

        // reduce partials across the 4 lanes of each group (cols are t-partitioned)
        #pragma unroll
        for (int m = 0; m < 2; m++)
            #pragma unroll
            for (int r = 0; r < 2; r++)
                #pragma unroll
                for (int c = 0; c < 3; c++) {
                    float v = o[m][r][c];
                    v += __shfl_xor_sync(0xFFFFFFFFu, v, 1);
                    v += __shfl_xor_sync(0xFFFFFFFFu, v, 2);
                    o[m][r][c] = v;
                }

        if (t == 0) {
            #pragma unroll
            for (int m = 0; m < 2; m++)
                #pragma unroll
                for (int r = 0; r < 2; r++) {
                    int idx = tile * 32 + 16 * m + 8 * r + g;
                    if (idx < n) {
                        out[3 * idx + 0] = o[m][r][0] + c0s;
                        out[3 * idx + 1] = o[m][r][1] + c1s;
                        out[3 * idx + 2] = o[m][r][2] + c2s;
                    }
                }
        }

        p_cur = p_next;
    }
}

extern "C" void kernel_launch(void* const* d_in, const int* in_sizes, int n_in,
                              void* d_out, int out_size)
{
    const float2* x    = (const float2*)d_in[0];
    const float*  hg0  = (const float*)d_in[1];
    const float*  hg1  = (const float*)d_in[2];
    // d_in[3] = kc0 (regular grid, analytic), d_in[4] = ks0 (== K-1)
    const float*  lc0  = (const float*)d_in[5];
    const float*  lcb0 = (const float*)d_in[6];
    const float*  W0   = (const float*)d_in[7];
    const float*  b0   = (const float*)d_in[8];
    const float*  W1   = (const float*)d_in[9];
    const float*  b1   = (const float*)d_in[10];
    const float*  W2   = (const float*)d_in[11];
    const float*  b2   = (const float*)d_in[12];
    const float*  a0   = (const float*)d_in[13];
    const float*  a1   = (const float*)d_in[14];
    const float*  a2   = (const float*)d_in[15];
    float* out = (float*)d_out;

    const int n = in_sizes[0] / 2;
    const int ntiles = (n + 31) / 32;
    int grid = 592;                       // 148 SMs x 4 blocks
    int maxg = (ntiles + 3) / 4;
    if (grid > maxg) grid = maxg;

    cudaFuncSetAttribute(rbf_mma_kernel, cudaFuncAttributeMaxDynamicSharedMemorySize, SMEM_BYTES);
    rbf_mma_kernel<<<grid, 128, SMEM_BYTES>>>(x, hg0, hg1, lc0, lcb0,
                                              W0, b0, W1, b1, W2, b2,
                                              a0, a1, a2, out, n, ntiles);
}